// round 3
// baseline (speedup 1.0000x reference)
#include <cuda_runtime.h>
#include <cuda_bf16.h>
#include <math.h>

// Problem shapes (fixed by the dataset): N=F=16384, M=4096, G=8192, S=16
#define MAXN     16384
#define MAXF     16384
#define MAXG     8192
#define SAMPLES  16
#define MAXQ     (MAXG * SAMPLES + MAXG)   // reverse sample points + forward barycenters

#define THREADS  256
#define TILE     2048   // float4 tile = 32 KB shared

// Scratch (static device globals — no allocation allowed)
__device__ float4 g_w[MAXN];     // original vertices:  (-2x, -2y, -2z, |v|^2)
__device__ float4 g_obw[MAXF];   // original barycenters, same transform
__device__ float4 g_q[MAXQ];     // queries: [0, G*S) = sample pts, [G*S, G*S+G) = simp barys; .w=|q|^2
__device__ double g_fwd;
__device__ double g_rev;
__device__ unsigned g_maxbits;   // bits of max distance (nonneg float -> monotone in uint)

// ---------------------------------------------------------------------------
// K1: preprocessing — transform vertices, barycenters, generate sample points,
//     zero accumulators.
// ---------------------------------------------------------------------------
__global__ void k_prep(const float* __restrict__ ov, const int* __restrict__ of,
                       const float* __restrict__ sv, const int* __restrict__ sf,
                       const float* __restrict__ r1, const float* __restrict__ r2,
                       int N, int F, int G, int S, int nq_rev)
{
    int idx = blockIdx.x * blockDim.x + threadIdx.x;
    if (idx == 0) {
        g_fwd = 0.0; g_rev = 0.0; g_maxbits = 0u;
    }
    if (idx < N) {
        float x = ov[3*idx+0], y = ov[3*idx+1], z = ov[3*idx+2];
        g_w[idx] = make_float4(-2.f*x, -2.f*y, -2.f*z, x*x + y*y + z*z);
    } else if (idx < N + F) {
        int f = idx - N;
        int i0 = of[3*f+0], i1 = of[3*f+1], i2 = of[3*f+2];
        float bx = (ov[3*i0+0] + ov[3*i1+0] + ov[3*i2+0]) * (1.f/3.f);
        float by = (ov[3*i0+1] + ov[3*i1+1] + ov[3*i2+1]) * (1.f/3.f);
        float bz = (ov[3*i0+2] + ov[3*i1+2] + ov[3*i2+2]) * (1.f/3.f);
        g_obw[f] = make_float4(-2.f*bx, -2.f*by, -2.f*bz, bx*bx + by*by + bz*bz);
    } else if (idx < N + F + G) {
        int g = idx - N - F;
        int i0 = sf[3*g+0], i1 = sf[3*g+1], i2 = sf[3*g+2];
        float ax = sv[3*i0+0], ay = sv[3*i0+1], az = sv[3*i0+2];
        float bx = sv[3*i1+0], by = sv[3*i1+1], bz = sv[3*i1+2];
        float cx = sv[3*i2+0], cy = sv[3*i2+1], cz = sv[3*i2+2];
        // simplified barycenter -> forward query
        {
            float sx = (ax+bx+cx) * (1.f/3.f);
            float sy = (ay+by+cy) * (1.f/3.f);
            float sz = (az+bz+cz) * (1.f/3.f);
            g_q[nq_rev + g] = make_float4(sx, sy, sz, sx*sx + sy*sy + sz*sz);
        }
        // S surface samples -> reverse queries
        for (int s = 0; s < S; s++) {
            float rr1 = r1[g*S + s];
            float rr2 = r2[g*S + s];
            float sq = sqrtf(rr1);
            float u = 1.f - sq;
            float v = sq * (1.f - rr2);
            float w = sq * rr2;
            float px = u*ax + v*bx + w*cx;
            float py = u*ay + v*by + w*cy;
            float pz = u*az + v*bz + w*cz;
            g_q[g*S + s] = make_float4(px, py, pz, px*px + py*py + pz*pz);
        }
    }
}

// ---------------------------------------------------------------------------
// K2: main min-distance kernel. Blocks [0, brev) handle reverse queries vs
// original vertices; blocks [brev, brev+bfwd) handle forward queries vs
// original barycenters. Each thread owns one query; refs tiled in smem.
// Fused block-reductions: sum contributions (-> g_rev / g_fwd), max distance
// for reverse (-> g_maxbits).
// ---------------------------------------------------------------------------
__global__ void __launch_bounds__(THREADS)
k_mindist(const float* __restrict__ probs,
          int brev, int nq_rev, int nq_fwd,
          int nref_rev, int nref_fwd, int S)
{
    __shared__ float4 sh[TILE];
    __shared__ float red_s[THREADS / 32];
    __shared__ float red_m[THREADS / 32];

    const int  tid = threadIdx.x;
    const bool rev = (blockIdx.x < (unsigned)brev);
    const float4* __restrict__ refs = rev ? g_w : g_obw;
    const int nref = rev ? nref_rev : nref_fwd;

    int qi; bool valid; float4 q;
    if (rev) {
        qi = blockIdx.x * THREADS + tid;
        valid = (qi < nq_rev);
        q = valid ? g_q[qi] : make_float4(0.f, 0.f, 0.f, 0.f);
    } else {
        qi = (blockIdx.x - brev) * THREADS + tid;
        valid = (qi < nq_fwd);
        q = valid ? g_q[nq_rev + qi] : make_float4(0.f, 0.f, 0.f, 0.f);
    }

    float best = 3.4e38f;
    for (int base = 0; base < nref; base += TILE) {
        const int cnt = nref - base;
        #pragma unroll
        for (int j = tid; j < TILE; j += THREADS)
            sh[j] = (j < cnt) ? refs[base + j] : make_float4(0.f, 0.f, 0.f, 3.0e38f);
        __syncthreads();

        #pragma unroll 8
        for (int j = 0; j < TILE; j++) {
            float4 w = sh[j];
            float d2 = fmaf(q.x, w.x, fmaf(q.y, w.y, fmaf(q.z, w.z, q.w + w.w)));
            best = fminf(best, d2);
        }
        __syncthreads();
    }

    float d = valid ? sqrtf(fmaxf(best, 1e-12f)) : 0.f;
    float contrib = 0.f;
    if (valid) {
        if (rev) {
            contrib = probs[qi / S] * d;
        } else {
            float p = probs[qi];
            contrib = p * d + 1e-4f * (1.f - p);
        }
    }

    // block-reduce sum(contrib) and (reverse only) max(d)
    float s = contrib;
    float m = d;
    #pragma unroll
    for (int o = 16; o > 0; o >>= 1) {
        s += __shfl_xor_sync(0xFFFFFFFFu, s, o);
        m = fmaxf(m, __shfl_xor_sync(0xFFFFFFFFu, m, o));
    }
    const int warp = tid >> 5, lane = tid & 31;
    if (lane == 0) { red_s[warp] = s; red_m[warp] = m; }
    __syncthreads();
    if (warp == 0) {
        s = (lane < (THREADS / 32)) ? red_s[lane] : 0.f;
        m = (lane < (THREADS / 32)) ? red_m[lane] : 0.f;
        #pragma unroll
        for (int o = (THREADS / 64); o > 0; o >>= 1) {
            s += __shfl_xor_sync(0xFFFFFFFFu, s, o);
            m = fmaxf(m, __shfl_xor_sync(0xFFFFFFFFu, m, o));
        }
        if (lane == 0) {
            atomicAdd(rev ? &g_rev : &g_fwd, (double)s);
            if (rev) atomicMax(&g_maxbits, __float_as_uint(m));
        }
    }
}

// ---------------------------------------------------------------------------
// K3: finalize scalar
// ---------------------------------------------------------------------------
__global__ void k_finalize(float* __restrict__ out)
{
    float maxd = __uint_as_float(g_maxbits) + 1e-8f;
    double result = g_fwd + g_rev * (0.1 / (double)maxd);
    out[0] = (float)result;
}

// ---------------------------------------------------------------------------
extern "C" void kernel_launch(void* const* d_in, const int* in_sizes, int n_in,
                              void* d_out, int out_size)
{
    const float* ov    = (const float*)d_in[0];
    const int*   of    = (const int*)  d_in[1];
    const float* sv    = (const float*)d_in[2];
    const int*   sf    = (const int*)  d_in[3];
    const float* probs = (const float*)d_in[4];
    const float* r1    = (const float*)d_in[5];
    const float* r2    = (const float*)d_in[6];

    const int N = in_sizes[0] / 3;     // 16384 original vertices
    const int F = in_sizes[1] / 3;     // 16384 original faces
    const int G = in_sizes[3] / 3;     // 8192 simplified faces
    const int S = in_sizes[5] / G;     // 16 samples per face

    const int nq_rev = G * S;          // 131072
    const int nq_fwd = G;              // 8192

    const int prep_items = N + F + G;
    k_prep<<<(prep_items + 255) / 256, 256>>>(ov, of, sv, sf, r1, r2, N, F, G, S, nq_rev);

    const int brev = (nq_rev + THREADS - 1) / THREADS;  // 512
    const int bfwd = (nq_fwd + THREADS - 1) / THREADS;  // 32
    k_mindist<<<brev + bfwd, THREADS>>>(probs, brev, nq_rev, nq_fwd, N, F, S);

    k_finalize<<<1, 1>>>((float*)d_out);
}

// round 4
// speedup vs baseline: 1.7054x; 1.7054x over previous
#include <cuda_runtime.h>
#include <cuda_bf16.h>
#include <math.h>

// Problem shapes (fixed by the dataset): N=F=16384, M=4096, G=8192, S=16
#define MAXN     16384
#define MAXF     16384
#define MAXG     8192
#define SAMPLES  16
#define MAXQ     (MAXG * SAMPLES + MAXG)

#define THREADS  256
#define QPT      2                    // queries per thread
#define QPB      (THREADS * QPT)     // 512 queries per block
#define TILE     2048                 // float4 slots = 32 KB smem = 2048 refs (1024 pairs)

// Reference points in PAIRED layout for packed f32x2 math:
//   pair j: float4[2j]   = {x0, x1, y0, y1}
//           float4[2j+1] = {z0, z1, w0, w1}
// where per-ref transform is (x,y,z,w) = (-2px, -2py, -2pz, |p|^2),
// so  s = fma(qx, x, fma(qy, y, fma(qz, z, w))) = |p|^2 - 2 q.p  (add |q|^2 later).
__device__ float4 g_wp[MAXN];    // original vertices, paired
__device__ float4 g_obp[MAXF];   // original barycenters, paired
__device__ float4 g_q[MAXQ];     // queries AoS: (x, y, z, |q|^2)
__device__ double g_fwd;
__device__ double g_rev;
__device__ unsigned g_maxbits;

// ---- packed f32x2 helpers ------------------------------------------------
__device__ __forceinline__ unsigned long long fma2(unsigned long long a,
                                                   unsigned long long b,
                                                   unsigned long long c) {
    unsigned long long d;
    asm("fma.rn.f32x2 %0, %1, %2, %3;" : "=l"(d) : "l"(a), "l"(b), "l"(c));
    return d;
}
__device__ __forceinline__ unsigned long long dup2(float v) {
    unsigned long long r;
    asm("mov.b64 %0, {%1, %1};" : "=l"(r) : "f"(v));
    return r;
}
__device__ __forceinline__ float2 u2f(unsigned long long v) {
    float2 f;
    asm("mov.b64 {%0, %1}, %2;" : "=f"(f.x), "=f"(f.y) : "l"(v));
    return f;
}

// ---------------------------------------------------------------------------
// K1: preprocessing — transformed refs in paired layout, sample points,
//     zero accumulators.
// ---------------------------------------------------------------------------
__global__ void k_prep(const float* __restrict__ ov, const int* __restrict__ of,
                       const float* __restrict__ sv, const int* __restrict__ sf,
                       const float* __restrict__ r1, const float* __restrict__ r2,
                       int N, int F, int G, int S, int nq_rev)
{
    int idx = blockIdx.x * blockDim.x + threadIdx.x;
    if (idx == 0) { g_fwd = 0.0; g_rev = 0.0; g_maxbits = 0u; }

    if (idx < N) {
        float x = ov[3*idx+0], y = ov[3*idx+1], z = ov[3*idx+2];
        float* p = reinterpret_cast<float*>(&g_wp[idx & ~1]);
        int o = idx & 1;
        p[0+o] = -2.f*x; p[2+o] = -2.f*y; p[4+o] = -2.f*z; p[6+o] = x*x + y*y + z*z;
    } else if (idx < N + F) {
        int f = idx - N;
        int i0 = of[3*f+0], i1 = of[3*f+1], i2 = of[3*f+2];
        float bx = (ov[3*i0+0] + ov[3*i1+0] + ov[3*i2+0]) * (1.f/3.f);
        float by = (ov[3*i0+1] + ov[3*i1+1] + ov[3*i2+1]) * (1.f/3.f);
        float bz = (ov[3*i0+2] + ov[3*i1+2] + ov[3*i2+2]) * (1.f/3.f);
        float* p = reinterpret_cast<float*>(&g_obp[f & ~1]);
        int o = f & 1;
        p[0+o] = -2.f*bx; p[2+o] = -2.f*by; p[4+o] = -2.f*bz; p[6+o] = bx*bx + by*by + bz*bz;
    } else if (idx < N + F + G) {
        int g = idx - N - F;
        int i0 = sf[3*g+0], i1 = sf[3*g+1], i2 = sf[3*g+2];
        float ax = sv[3*i0+0], ay = sv[3*i0+1], az = sv[3*i0+2];
        float bx = sv[3*i1+0], by = sv[3*i1+1], bz = sv[3*i1+2];
        float cx = sv[3*i2+0], cy = sv[3*i2+1], cz = sv[3*i2+2];
        {
            float sx = (ax+bx+cx) * (1.f/3.f);
            float sy = (ay+by+cy) * (1.f/3.f);
            float sz = (az+bz+cz) * (1.f/3.f);
            g_q[nq_rev + g] = make_float4(sx, sy, sz, sx*sx + sy*sy + sz*sz);
        }
        for (int s = 0; s < S; s++) {
            float rr1 = r1[g*S + s];
            float rr2 = r2[g*S + s];
            float sq = sqrtf(rr1);
            float u = 1.f - sq;
            float v = sq * (1.f - rr2);
            float w = sq * rr2;
            float px = u*ax + v*bx + w*cx;
            float py = u*ay + v*by + w*cy;
            float pz = u*az + v*bz + w*cz;
            g_q[g*S + s] = make_float4(px, py, pz, px*px + py*py + pz*pz);
        }
    }
}

// ---------------------------------------------------------------------------
// K2: min-distance. 2 queries/thread, refs in smem as packed pairs,
// inner loop = packed f32x2 FMA chains (2 refs per chain).
// ---------------------------------------------------------------------------
__global__ void __launch_bounds__(THREADS)
k_mindist(const float* __restrict__ probs,
          int brev, int nq_rev, int nq_fwd,
          int nref_rev, int nref_fwd, int S)
{
    __shared__ float4 sh[TILE];
    __shared__ float red_s[THREADS / 32];
    __shared__ float red_m[THREADS / 32];

    const int  tid = threadIdx.x;
    const bool rev = (blockIdx.x < (unsigned)brev);
    const float4* __restrict__ refs = rev ? g_wp : g_obp;
    const int nref = rev ? nref_rev : nref_fwd;       // refs == float4 slots (16B/ref)
    const int nq   = rev ? nq_rev : nq_fwd;
    const int qoff = rev ? 0 : nq_rev;
    const int qbase = (rev ? blockIdx.x : blockIdx.x - brev) * QPB;

    const int qiA = qbase + tid;
    const int qiB = qbase + tid + THREADS;
    const bool vA = (qiA < nq);
    const bool vB = (qiB < nq);
    float4 qA = vA ? g_q[qoff + qiA] : make_float4(0.f, 0.f, 0.f, 0.f);
    float4 qB = vB ? g_q[qoff + qiB] : make_float4(0.f, 0.f, 0.f, 0.f);

    const unsigned long long xA = dup2(qA.x), yA = dup2(qA.y), zA = dup2(qA.z);
    const unsigned long long xB = dup2(qB.x), yB = dup2(qB.y), zB = dup2(qB.z);

    float bA0 = 3.4e38f, bA1 = 3.4e38f, bB0 = 3.4e38f, bB1 = 3.4e38f;

    const ulonglong2* shp = reinterpret_cast<const ulonglong2*>(sh);

    for (int base = 0; base < nref; base += TILE) {
        const int cnt = nref - base;
        #pragma unroll
        for (int j = tid; j < TILE; j += THREADS) {
            if (j < cnt) sh[j] = refs[base + j];
            else         sh[j] = (j & 1) ? make_float4(0.f, 0.f, 3.0e38f, 3.0e38f)
                                         : make_float4(0.f, 0.f, 0.f, 0.f);
        }
        __syncthreads();

        #pragma unroll 8
        for (int j = 0; j < TILE/2; j++) {
            ulonglong2 P = shp[2*j];       // (x0x1, y0y1)
            ulonglong2 Q = shp[2*j+1];     // (z0z1, w0w1)
            unsigned long long t = fma2(zA, Q.x, Q.y);
            t = fma2(yA, P.y, t);
            t = fma2(xA, P.x, t);
            float2 s = u2f(t);
            bA0 = fminf(bA0, s.x); bA1 = fminf(bA1, s.y);

            unsigned long long u = fma2(zB, Q.x, Q.y);
            u = fma2(yB, P.y, u);
            u = fma2(xB, P.x, u);
            float2 r = u2f(u);
            bB0 = fminf(bB0, r.x); bB1 = fminf(bB1, r.y);
        }
        __syncthreads();
    }

    float dA = 0.f, dB = 0.f, cA = 0.f, cB = 0.f;
    if (vA) {
        dA = sqrtf(fmaxf(fminf(bA0, bA1) + qA.w, 1e-12f));
        if (rev) cA = probs[qiA / S] * dA;
        else { float p = probs[qiA]; cA = p * dA + 1e-4f * (1.f - p); }
    }
    if (vB) {
        dB = sqrtf(fmaxf(fminf(bB0, bB1) + qB.w, 1e-12f));
        if (rev) cB = probs[qiB / S] * dB;
        else { float p = probs[qiB]; cB = p * dB + 1e-4f * (1.f - p); }
    }

    // block-reduce sum(contrib) and (reverse only) max(d)
    float s = cA + cB;
    float m = fmaxf(dA, dB);
    #pragma unroll
    for (int o = 16; o > 0; o >>= 1) {
        s += __shfl_xor_sync(0xFFFFFFFFu, s, o);
        m = fmaxf(m, __shfl_xor_sync(0xFFFFFFFFu, m, o));
    }
    const int warp = tid >> 5, lane = tid & 31;
    if (lane == 0) { red_s[warp] = s; red_m[warp] = m; }
    __syncthreads();
    if (warp == 0) {
        s = (lane < (THREADS / 32)) ? red_s[lane] : 0.f;
        m = (lane < (THREADS / 32)) ? red_m[lane] : 0.f;
        #pragma unroll
        for (int o = (THREADS / 64); o > 0; o >>= 1) {
            s += __shfl_xor_sync(0xFFFFFFFFu, s, o);
            m = fmaxf(m, __shfl_xor_sync(0xFFFFFFFFu, m, o));
        }
        if (lane == 0) {
            atomicAdd(rev ? &g_rev : &g_fwd, (double)s);
            if (rev) atomicMax(&g_maxbits, __float_as_uint(m));
        }
    }
}

// ---------------------------------------------------------------------------
// K3: finalize scalar
// ---------------------------------------------------------------------------
__global__ void k_finalize(float* __restrict__ out)
{
    float maxd = __uint_as_float(g_maxbits) + 1e-8f;
    double result = g_fwd + g_rev * (0.1 / (double)maxd);
    out[0] = (float)result;
}

// ---------------------------------------------------------------------------
extern "C" void kernel_launch(void* const* d_in, const int* in_sizes, int n_in,
                              void* d_out, int out_size)
{
    const float* ov    = (const float*)d_in[0];
    const int*   of    = (const int*)  d_in[1];
    const float* sv    = (const float*)d_in[2];
    const int*   sf    = (const int*)  d_in[3];
    const float* probs = (const float*)d_in[4];
    const float* r1    = (const float*)d_in[5];
    const float* r2    = (const float*)d_in[6];

    const int N = in_sizes[0] / 3;     // 16384
    const int F = in_sizes[1] / 3;     // 16384
    const int G = in_sizes[3] / 3;     // 8192
    const int S = in_sizes[5] / G;     // 16

    const int nq_rev = G * S;          // 131072
    const int nq_fwd = G;              // 8192

    const int prep_items = N + F + G;
    k_prep<<<(prep_items + 255) / 256, 256>>>(ov, of, sv, sf, r1, r2, N, F, G, S, nq_rev);

    const int brev = (nq_rev + QPB - 1) / QPB;   // 256
    const int bfwd = (nq_fwd + QPB - 1) / QPB;   // 16
    k_mindist<<<brev + bfwd, THREADS>>>(probs, brev, nq_rev, nq_fwd, N, F, S);

    k_finalize<<<1, 1>>>((float*)d_out);
}

// round 6
// speedup vs baseline: 1.8451x; 1.0819x over previous
#include <cuda_runtime.h>
#include <cuda_bf16.h>
#include <math.h>

// Problem shapes (fixed dataset): N=F=16384, G=8192, S=16
#define MAXN    16384
#define MAXF    16384
#define MAXG    8192
#define SMP     16
#define MAXQR   (MAXG * SMP)        // 131072 reverse queries

// Uniform grid over [-4.75, 4.75]^3. Refs/queries outside are clamped into
// edge cells (conservative: clamping only pushes points outward, so the
// shell termination bound  d_best <= r*h  stays sound).
#define GD      48
#define CELLS   (GD * GD * GD)      // 110592
#define LOB     (-4.75f)
#define HCELL   (9.5f / (float)GD)  // ~0.19792
#define SCANT   1024
#define PERT    (CELLS / SCANT)     // 108 (divides exactly)

// set 0: original vertices (refs for reverse)
// set 1: original barycenters (refs for forward)
// set 2: reverse sample-point queries
// set 3: forward barycenter queries
__device__ int    g_cnt[4][CELLS];
__device__ int    g_starts[4][CELLS + 1];
__device__ int    g_cursor[4][CELLS];
__device__ float4 g_sref0[MAXN];    // (x,y,z,|p|^2) sorted by cell
__device__ float4 g_sref1[MAXF];
__device__ float4 g_sq0[MAXQR];     // (x,y,z,|q|^2) sorted by cell
__device__ float  g_sp0[MAXQR];     // prob per sorted reverse query
__device__ float4 g_sq1[MAXG];
__device__ float  g_sp1[MAXG];
__device__ double g_fwd, g_rev;
__device__ unsigned g_maxbits;

__device__ __forceinline__ int cellof(float x) {
    int c = (int)floorf((x - LOB) * (1.0f / HCELL));
    return min(max(c, 0), GD - 1);
}

// Deterministic item generator shared by count & fill passes.
__device__ __forceinline__ void item(
    int idx,
    const float* __restrict__ ov, const int* __restrict__ of,
    const float* __restrict__ sv, const int* __restrict__ sf,
    const float* __restrict__ probs,
    const float* __restrict__ r1, const float* __restrict__ r2,
    int N, int F, int G, int S,
    int& set, float& x, float& y, float& z, float& prob)
{
    if (idx < N) {
        set = 0; prob = 0.f;
        x = ov[3*idx]; y = ov[3*idx+1]; z = ov[3*idx+2];
    } else if (idx < N + F) {
        set = 1; prob = 0.f;
        int f = idx - N;
        int i0 = of[3*f], i1 = of[3*f+1], i2 = of[3*f+2];
        x = (ov[3*i0  ] + ov[3*i1  ] + ov[3*i2  ]) * (1.f/3.f);
        y = (ov[3*i0+1] + ov[3*i1+1] + ov[3*i2+1]) * (1.f/3.f);
        z = (ov[3*i0+2] + ov[3*i1+2] + ov[3*i2+2]) * (1.f/3.f);
    } else if (idx < N + F + G * S) {
        set = 2;
        int q = idx - N - F;
        int g = q / S;
        int i0 = sf[3*g], i1 = sf[3*g+1], i2 = sf[3*g+2];
        float sq = sqrtf(r1[q]);
        float rr2 = r2[q];
        float u = 1.f - sq, v = sq * (1.f - rr2), w = sq * rr2;
        x = u*sv[3*i0  ] + v*sv[3*i1  ] + w*sv[3*i2  ];
        y = u*sv[3*i0+1] + v*sv[3*i1+1] + w*sv[3*i2+1];
        z = u*sv[3*i0+2] + v*sv[3*i1+2] + w*sv[3*i2+2];
        prob = probs[g];
    } else {
        set = 3;
        int g = idx - N - F - G * S;
        int i0 = sf[3*g], i1 = sf[3*g+1], i2 = sf[3*g+2];
        x = (sv[3*i0  ] + sv[3*i1  ] + sv[3*i2  ]) * (1.f/3.f);
        y = (sv[3*i0+1] + sv[3*i1+1] + sv[3*i2+1]) * (1.f/3.f);
        z = (sv[3*i0+2] + sv[3*i1+2] + sv[3*i2+2]) * (1.f/3.f);
        prob = probs[g];
    }
}

// ---------------------------------------------------------------------------
__global__ void k_zero()
{
    int idx = blockIdx.x * blockDim.x + threadIdx.x;
    if (idx == 0) { g_fwd = 0.0; g_rev = 0.0; g_maxbits = 0u; }
    if (idx < 4 * CELLS) ((int*)g_cnt)[idx] = 0;
}

__global__ void k_count(const float* __restrict__ ov, const int* __restrict__ of,
                        const float* __restrict__ sv, const int* __restrict__ sf,
                        const float* __restrict__ probs,
                        const float* __restrict__ r1, const float* __restrict__ r2,
                        int N, int F, int G, int S, int T)
{
    int idx = blockIdx.x * blockDim.x + threadIdx.x;
    if (idx >= T) return;
    int set; float x, y, z, p;
    item(idx, ov, of, sv, sf, probs, r1, r2, N, F, G, S, set, x, y, z, p);
    int cid = (cellof(z) * GD + cellof(y)) * GD + cellof(x);
    atomicAdd(&g_cnt[set][cid], 1);
}

__global__ void k_scan()
{
    const int a = blockIdx.x;     // which of the 4 arrays
    const int t = threadIdx.x;
    __shared__ int part[SCANT];
    const int base = t * PERT;
    int sum = 0;
    #pragma unroll 4
    for (int i = 0; i < PERT; i++) sum += g_cnt[a][base + i];
    part[t] = sum;
    __syncthreads();
    for (int off = 1; off < SCANT; off <<= 1) {
        int v = (t >= off) ? part[t - off] : 0;
        __syncthreads();
        part[t] += v;
        __syncthreads();
    }
    int run = part[t] - sum;      // exclusive prefix
    for (int i = 0; i < PERT; i++) {
        int c = g_cnt[a][base + i];
        g_starts[a][base + i] = run;
        g_cursor[a][base + i] = run;
        run += c;
    }
    if (t == SCANT - 1) g_starts[a][CELLS] = run;
}

__global__ void k_fill(const float* __restrict__ ov, const int* __restrict__ of,
                       const float* __restrict__ sv, const int* __restrict__ sf,
                       const float* __restrict__ probs,
                       const float* __restrict__ r1, const float* __restrict__ r2,
                       int N, int F, int G, int S, int T)
{
    int idx = blockIdx.x * blockDim.x + threadIdx.x;
    if (idx >= T) return;
    int set; float x, y, z, p;
    item(idx, ov, of, sv, sf, probs, r1, r2, N, F, G, S, set, x, y, z, p);
    int cid = (cellof(z) * GD + cellof(y)) * GD + cellof(x);
    int pos = atomicAdd(&g_cursor[set][cid], 1);
    float ww = x*x + y*y + z*z;
    float4 v4 = make_float4(x, y, z, ww);
    if      (set == 0) g_sref0[pos] = v4;
    else if (set == 1) g_sref1[pos] = v4;
    else if (set == 2) { g_sq0[pos] = v4; g_sp0[pos] = p; }
    else               { g_sq1[pos] = v4; g_sp1[pos] = p; }
}

// ---------------------------------------------------------------------------
// Grid NN query. which=0: reverse (sample pts vs orig vertices),
//                which=1: forward (simp barycenters vs orig barycenters).
// ---------------------------------------------------------------------------
#define QTHREADS 128
__global__ void __launch_bounds__(QTHREADS)
k_query(int which, int nq)
{
    const float4* __restrict__ refs  = which ? g_sref1     : g_sref0;
    const int*    __restrict__ st    = which ? g_starts[1] : g_starts[0];
    const float4* __restrict__ qarr  = which ? g_sq1       : g_sq0;
    const float*  __restrict__ parr  = which ? g_sp1       : g_sp0;

    const int qi = blockIdx.x * blockDim.x + threadIdx.x;
    float contrib = 0.f, d = 0.f;

    if (qi < nq) {
        float4 Q = qarr[qi];
        const float a = -2.f * Q.x, b = -2.f * Q.y, c = -2.f * Q.z;
        const float qq = Q.w;
        const int cx = cellof(Q.x), cy = cellof(Q.y), cz = cellof(Q.z);

        float best = 3.4e38f;   // best (|p|^2 - 2 q.p); d^2 = best + qq
        for (int r = 0; r < GD; r++) {
            const int x0 = max(cx - r, 0), x1 = min(cx + r, GD - 1);
            const int y0 = max(cy - r, 0), y1 = min(cy + r, GD - 1);
            const int z0 = max(cz - r, 0), z1 = min(cz + r, GD - 1);
            const int xr = x1 - x0;

            for (int z = z0; z <= z1; z++) {
                const bool zface = (z == cz - r) || (z == cz + r);
                for (int y = y0; y <= y1; y++) {
                    const bool face = zface || (y == cy - r) || (y == cy + r);
                    if (face) {
                        // full contiguous row of cells
                        const int c0 = (z * GD + y) * GD + x0;
                        const int s = st[c0], e = st[c0 + xr + 1];
                        for (int i = s; i < e; i++) {
                            float4 w = refs[i];
                            float t = fmaf(a, w.x, fmaf(b, w.y, fmaf(c, w.z, w.w)));
                            best = fminf(best, t);
                        }
                    } else {
                        // just the two x-extreme cells of this row
                        if (cx - r >= 0) {
                            const int cc = (z * GD + y) * GD + (cx - r);
                            const int s = st[cc], e = st[cc + 1];
                            for (int i = s; i < e; i++) {
                                float4 w = refs[i];
                                float t = fmaf(a, w.x, fmaf(b, w.y, fmaf(c, w.z, w.w)));
                                best = fminf(best, t);
                            }
                        }
                        if (cx + r <= GD - 1) {
                            const int cc = (z * GD + y) * GD + (cx + r);
                            const int s = st[cc], e = st[cc + 1];
                            for (int i = s; i < e; i++) {
                                float4 w = refs[i];
                                float t = fmaf(a, w.x, fmaf(b, w.y, fmaf(c, w.z, w.w)));
                                best = fminf(best, t);
                            }
                        }
                    }
                }
            }
            // Termination: all unscanned cells lie at Chebyshev >= r+1,
            // so any unscanned point is at distance >= r*h.
            const float d2 = fmaxf(best + qq, 0.f);
            const float cov = (float)r * HCELL;
            if (d2 <= cov * cov) break;
            if (x0 == 0 && y0 == 0 && z0 == 0 &&
                x1 == GD - 1 && y1 == GD - 1 && z1 == GD - 1) break;
        }

        d = sqrtf(fmaxf(best + qq, 1e-12f));
        const float p = parr[qi];
        contrib = which ? fmaf(p, d, 1e-4f * (1.f - p)) : p * d;
    }

    // block reduce: sum(contrib), and max(d) for reverse
    __shared__ float red_s[QTHREADS / 32];
    __shared__ float red_m[QTHREADS / 32];
    float s = contrib, m = d;
    #pragma unroll
    for (int o = 16; o > 0; o >>= 1) {
        s += __shfl_xor_sync(0xFFFFFFFFu, s, o);
        m = fmaxf(m, __shfl_xor_sync(0xFFFFFFFFu, m, o));
    }
    const int warp = threadIdx.x >> 5, lane = threadIdx.x & 31;
    if (lane == 0) { red_s[warp] = s; red_m[warp] = m; }
    __syncthreads();
    if (warp == 0) {
        s = (lane < (QTHREADS / 32)) ? red_s[lane] : 0.f;
        m = (lane < (QTHREADS / 32)) ? red_m[lane] : 0.f;
        #pragma unroll
        for (int o = (QTHREADS / 64); o > 0; o >>= 1) {
            s += __shfl_xor_sync(0xFFFFFFFFu, s, o);
            m = fmaxf(m, __shfl_xor_sync(0xFFFFFFFFu, m, o));
        }
        if (lane == 0) {
            atomicAdd(which ? &g_fwd : &g_rev, (double)s);
            if (!which) atomicMax(&g_maxbits, __float_as_uint(m));
        }
    }
}

// ---------------------------------------------------------------------------
__global__ void k_finalize(float* __restrict__ out)
{
    float maxd = __uint_as_float(g_maxbits) + 1e-8f;
    double result = g_fwd + g_rev * (0.1 / (double)maxd);
    out[0] = (float)result;
}

// ---------------------------------------------------------------------------
extern "C" void kernel_launch(void* const* d_in, const int* in_sizes, int n_in,
                              void* d_out, int out_size)
{
    const float* ov    = (const float*)d_in[0];
    const int*   of    = (const int*)  d_in[1];
    const float* sv    = (const float*)d_in[2];
    const int*   sf    = (const int*)  d_in[3];
    const float* probs = (const float*)d_in[4];
    const float* r1    = (const float*)d_in[5];
    const float* r2    = (const float*)d_in[6];

    const int N = in_sizes[0] / 3;     // 16384
    const int F = in_sizes[1] / 3;     // 16384
    const int G = in_sizes[3] / 3;     // 8192
    const int S = in_sizes[5] / G;     // 16

    const int nq_rev = G * S;          // 131072
    const int nq_fwd = G;              // 8192
    const int T = N + F + nq_rev + nq_fwd;   // 172032

    k_zero <<<(4 * CELLS + 255) / 256, 256>>>();
    k_count<<<(T + 255) / 256, 256>>>(ov, of, sv, sf, probs, r1, r2, N, F, G, S, T);
    k_scan <<<4, SCANT>>>();
    k_fill <<<(T + 255) / 256, 256>>>(ov, of, sv, sf, probs, r1, r2, N, F, G, S, T);

    k_query<<<(nq_rev + QTHREADS - 1) / QTHREADS, QTHREADS>>>(0, nq_rev);
    k_query<<<(nq_fwd + QTHREADS - 1) / QTHREADS, QTHREADS>>>(1, nq_fwd);

    k_finalize<<<1, 1>>>((float*)d_out);
}